// round 4
// baseline (speedup 1.0000x reference)
#include <cuda_runtime.h>
#include <cuda_fp16.h>
#include <cstdint>

// Problem constants
#define NA 4096
#define NB 4096
#define DD 256
#define HH 4
#define DK 64

// Scratch: projected Q/K/V in fp16 (2 MB each) — __device__ globals (no allocs allowed)
__device__ __half g_Q[NA * DD];
__device__ __half g_K[NB * DD];
__device__ __half g_V[NB * DD];

__device__ __forceinline__ void mma16816(float c[4], const uint32_t a[4],
                                         uint32_t b0, uint32_t b1) {
    asm volatile(
        "mma.sync.aligned.m16n8k16.row.col.f32.f16.f16.f32 "
        "{%0,%1,%2,%3}, {%4,%5,%6,%7}, {%8,%9}, {%0,%1,%2,%3};\n"
        : "+f"(c[0]), "+f"(c[1]), "+f"(c[2]), "+f"(c[3])
        : "r"(a[0]), "r"(a[1]), "r"(a[2]), "r"(a[3]), "r"(b0), "r"(b1));
}

__device__ __forceinline__ uint32_t packh2(float x, float y) {
    __half2 t = __floats2half2_rn(x, y);
    return *reinterpret_cast<uint32_t*>(&t);
}

// ---------------------------------------------------------------------------
// Kernel 1: projections  Y = X @ W^T  (fp32 in, fp16 out), 3 GEMMs via grid.z
// BM=64, BN=64, BK=16, 128 threads (2x2 warps, each warp 32x32)
// ---------------------------------------------------------------------------
__global__ __launch_bounds__(128) void proj_kernel(
    const float* __restrict__ a_z, const float* __restrict__ bv_z,
    const float* __restrict__ Wq, const float* __restrict__ Wk,
    const float* __restrict__ Wv) {
    const float* X;
    const float* W;
    __half* Y;
    int z = blockIdx.z;
    if (z == 0)      { X = a_z;  W = Wq; Y = g_Q; }
    else if (z == 1) { X = bv_z; W = Wk; Y = g_K; }
    else             { X = bv_z; W = Wv; Y = g_V; }

    const int a0 = blockIdx.x * 64;
    const int n0 = blockIdx.y * 64;

    __shared__ __half sA[64][24];  // pad 24 -> conflict-free frag loads
    __shared__ __half sB[64][24];

    const int tid = threadIdx.x;
    const int lane = tid & 31, warp = tid >> 5;
    const int gr = lane >> 2, tig = lane & 3;
    const int wm = warp >> 1, wn = warp & 1;

    float acc[2][4][4] = {};

    for (int kt = 0; kt < DD / 16; kt++) {
        __syncthreads();
        // stage A (X rows) and B (W rows) tiles, fp32 -> fp16
#pragma unroll
        for (int i = 0; i < 2; i++) {
            int j = tid + i * 128;
            int row = j >> 2, c4 = (j & 3) * 4;
            float4 xa = *(const float4*)&X[(size_t)(a0 + row) * DD + kt * 16 + c4];
            *(__half2*)&sA[row][c4]     = __floats2half2_rn(xa.x, xa.y);
            *(__half2*)&sA[row][c4 + 2] = __floats2half2_rn(xa.z, xa.w);
            float4 xb = *(const float4*)&W[(size_t)(n0 + row) * DD + kt * 16 + c4];
            *(__half2*)&sB[row][c4]     = __floats2half2_rn(xb.x, xb.y);
            *(__half2*)&sB[row][c4 + 2] = __floats2half2_rn(xb.z, xb.w);
        }
        __syncthreads();

        uint32_t af[2][4];
#pragma unroll
        for (int mt = 0; mt < 2; mt++) {
            const __half* p = &sA[wm * 32 + mt * 16 + gr][tig * 2];
            af[mt][0] = *(const uint32_t*)p;
            af[mt][1] = *(const uint32_t*)(p + 8 * 24);
            af[mt][2] = *(const uint32_t*)(p + 8);
            af[mt][3] = *(const uint32_t*)(p + 8 * 24 + 8);
        }
#pragma unroll
        for (int nt = 0; nt < 4; nt++) {
            const __half* p = &sB[wn * 32 + nt * 8 + gr][tig * 2];
            uint32_t b0 = *(const uint32_t*)p;
            uint32_t b1 = *(const uint32_t*)(p + 8);
            mma16816(acc[0][nt], af[0], b0, b1);
            mma16816(acc[1][nt], af[1], b0, b1);
        }
    }

    // epilogue: fp32 accum -> fp16 store
#pragma unroll
    for (int mt = 0; mt < 2; mt++)
#pragma unroll
        for (int nt = 0; nt < 4; nt++) {
            int row = a0 + wm * 32 + mt * 16 + gr;
            int col = n0 + wn * 32 + nt * 8 + tig * 2;
            __half2 lo = __floats2half2_rn(acc[mt][nt][0], acc[mt][nt][1]);
            __half2 hi = __floats2half2_rn(acc[mt][nt][2], acc[mt][nt][3]);
            *(__half2*)&Y[(size_t)row * DD + col] = lo;
            *(__half2*)&Y[(size_t)(row + 8) * DD + col] = hi;
        }
}

// ---------------------------------------------------------------------------
// Kernel 2: fused attention. 128 CTAs x 128 threads; warp = head.
// Per CTA: BM=32 A-rows, loop over 128 b-tiles of BN=32.
// No online softmax needed: logits clipped to [-10,10] -> direct exp-accumulate.
// ---------------------------------------------------------------------------
#define SK_STRIDE 264   // halves; 132 words -> conflict-free
#define SVT_STRIDE 40   // halves; 20 words -> conflict-free
#define SW_STRIDE 36    // floats; 16B aligned rows

#define OFF_SVT (32 * SK_STRIDE * 2)                 // 16896
#define OFF_SW  (OFF_SVT + 256 * SVT_STRIDE * 2)     // 16896 + 20480 = 37376
#define SMEM_BYTES (OFF_SW + 32 * SW_STRIDE * 4)     // + 4608 = 41984

__global__ __launch_bounds__(128) void attn_kernel(
    const int* __restrict__ mask, const float* __restrict__ weight,
    float* __restrict__ out) {
    __shared__ __align__(16) unsigned char smem_raw[SMEM_BYTES];
    __half (*sK)[SK_STRIDE]  = reinterpret_cast<__half(*)[SK_STRIDE]>(smem_raw);
    __half (*sVt)[SVT_STRIDE] = reinterpret_cast<__half(*)[SVT_STRIDE]>(smem_raw + OFF_SVT);
    float (*sW)[SW_STRIDE]   = reinterpret_cast<float(*)[SW_STRIDE]>(smem_raw + OFF_SW);
    // ctx reduce buffer reuses the sK+sVt region after the mainloop (33280 B <= 37376 B)
    float (*ctx)[32][65]     = reinterpret_cast<float(*)[32][65]>(smem_raw);

    const int tid = threadIdx.x;
    const int lane = tid & 31;
    const int h = tid >> 5;          // warp == head
    const int gr = lane >> 2, tig = lane & 3;
    const int a0 = blockIdx.x * 32;

    // Preload Q fragments for this head: [32 rows][64 k] -> 2 mtiles x 4 ksteps x 4 regs
    uint32_t qf[2][4][4];
#pragma unroll
    for (int mt = 0; mt < 2; mt++)
#pragma unroll
        for (int ks = 0; ks < 4; ks++) {
            const __half* q = &g_Q[(size_t)(a0 + mt * 16 + gr) * DD + h * DK + ks * 16 + tig * 2];
            qf[mt][ks][0] = *(const uint32_t*)q;
            qf[mt][ks][1] = *(const uint32_t*)(q + 8 * DD);
            qf[mt][ks][2] = *(const uint32_t*)(q + 8);
            qf[mt][ks][3] = *(const uint32_t*)(q + 8 * DD + 8);
        }

    float cacc[2][8][4] = {};   // context numerator [32 rows][64 dk] fp32
    float den[2][2] = {};       // per-thread softmax denominators

    for (int bt = 0; bt < NB / 32; bt++) {
        const int b0 = bt * 32;
        __syncthreads();
        // ---- stage K (row-major) and V (transposed) in fp16 ----
#pragma unroll
        for (int i = 0; i < 8; i++) {
            int j = tid + i * 128;
            int row = j >> 5, colh = (j & 31) * 8;
            uint4 kv = *(const uint4*)&g_K[(size_t)(b0 + row) * DD + colh];
            *(uint4*)&sK[row][colh] = kv;
            uint4 vv = *(const uint4*)&g_V[(size_t)(b0 + row) * DD + colh];
            const __half* vh = (const __half*)&vv;
#pragma unroll
            for (int t2 = 0; t2 < 8; t2++) sVt[colh + t2][row] = vh[t2];
        }
        // ---- stage weight with mask folded in: masked -> -1e30 (clips to -10) ----
        // mask is int32 (bool promoted by the harness dtype palette)
#pragma unroll
        for (int i = 0; i < 2; i++) {
            int j = tid + i * 128;
            int row = j >> 3, c4 = (j & 7) * 4;
            float4 w4 = *(const float4*)&weight[(size_t)(a0 + row) * NB + b0 + c4];
            int4   m4 = *(const int4*)&mask[(size_t)(a0 + row) * NB + b0 + c4];
            sW[row][c4 + 0] = m4.x ? w4.x : -1e30f;
            sW[row][c4 + 1] = m4.y ? w4.y : -1e30f;
            sW[row][c4 + 2] = m4.z ? w4.z : -1e30f;
            sW[row][c4 + 3] = m4.w ? w4.w : -1e30f;
        }
        __syncthreads();

        // ---- S = Q K^T (this head) ----
        float sacc[2][4][4] = {};
#pragma unroll
        for (int nt = 0; nt < 4; nt++)
#pragma unroll
            for (int ks = 0; ks < 4; ks++) {
                const __half* kb = &sK[nt * 8 + gr][h * DK + ks * 16 + tig * 2];
                uint32_t kb0 = *(const uint32_t*)kb;
                uint32_t kb1 = *(const uint32_t*)(kb + 8);
                mma16816(sacc[0][nt], qf[0][ks], kb0, kb1);
                mma16816(sacc[1][nt], qf[1][ks], kb0, kb1);
            }

        // ---- t = clip(s/8 + w_or_-1e30, -10, 10); p = exp(t); pack P as fp16 A-frags ----
        uint32_t pa[2][2][4];
#pragma unroll
        for (int mt = 0; mt < 2; mt++)
#pragma unroll
            for (int nt = 0; nt < 4; nt++) {
                int ra = mt * 16 + gr;
                int cb = nt * 8 + tig * 2;
                float2 w0 = *(const float2*)&sW[ra][cb];
                float2 w1 = *(const float2*)&sW[ra + 8][cb];
                float p0 = __expf(fmaxf(fminf(sacc[mt][nt][0] * 0.125f + w0.x, 10.f), -10.f));
                float p1 = __expf(fmaxf(fminf(sacc[mt][nt][1] * 0.125f + w0.y, 10.f), -10.f));
                float p2 = __expf(fmaxf(fminf(sacc[mt][nt][2] * 0.125f + w1.x, 10.f), -10.f));
                float p3 = __expf(fmaxf(fminf(sacc[mt][nt][3] * 0.125f + w1.y, 10.f), -10.f));
                den[mt][0] += p0 + p1;
                den[mt][1] += p2 + p3;
                int kk = nt >> 1, hf = nt & 1;
                pa[mt][kk][hf * 2 + 0] = packh2(p0, p1);
                pa[mt][kk][hf * 2 + 1] = packh2(p2, p3);
            }

        // ---- context += P @ V (V transposed in smem: B[k=b][n=d] = sVt[d][b]) ----
#pragma unroll
        for (int nt = 0; nt < 8; nt++) {
            int dd = h * DK + nt * 8 + gr;
#pragma unroll
            for (int kk = 0; kk < 2; kk++) {
                const __half* vb = &sVt[dd][kk * 16 + tig * 2];
                uint32_t vb0 = *(const uint32_t*)vb;
                uint32_t vb1 = *(const uint32_t*)(vb + 8);
                mma16816(cacc[0][nt], pa[0][kk], vb0, vb1);
                mma16816(cacc[1][nt], pa[1][kk], vb0, vb1);
            }
        }
    }

    // ---- reduce denominators across the 4 lanes of each row-group ----
#pragma unroll
    for (int mt = 0; mt < 2; mt++)
#pragma unroll
        for (int r2 = 0; r2 < 2; r2++) {
            den[mt][r2] += __shfl_xor_sync(0xffffffffu, den[mt][r2], 1);
            den[mt][r2] += __shfl_xor_sync(0xffffffffu, den[mt][r2], 2);
        }
    float inv[2][2];
#pragma unroll
    for (int mt = 0; mt < 2; mt++) {
        inv[mt][0] = 1.0f / den[mt][0];
        inv[mt][1] = 1.0f / den[mt][1];
    }

    __syncthreads();  // all warps done reading sK/sVt before ctx reuse

#pragma unroll
    for (int mt = 0; mt < 2; mt++)
#pragma unroll
        for (int nt = 0; nt < 8; nt++) {
            int ra = mt * 16 + gr;
            int dc = nt * 8 + tig * 2;
            ctx[h][ra][dc]         = cacc[mt][nt][0] * inv[mt][0];
            ctx[h][ra][dc + 1]     = cacc[mt][nt][1] * inv[mt][0];
            ctx[h][ra + 8][dc]     = cacc[mt][nt][2] * inv[mt][1];
            ctx[h][ra + 8][dc + 1] = cacc[mt][nt][3] * inv[mt][1];
        }
    __syncthreads();

    // topic_align = mean over heads
#pragma unroll
    for (int i = 0; i < 16; i++) {
        int e = tid + i * 128;
        int a = e >> 6, dcol = e & 63;
        out[(size_t)(a0 + a) * DK + dcol] =
            0.25f * (ctx[0][a][dcol] + ctx[1][a][dcol] + ctx[2][a][dcol] + ctx[3][a][dcol]);
    }
    // influence = mean_h(sum_b softmax) == 1.0 (ref deviates only by fp roundoff ~1e-6)
    if (tid < 32) out[(size_t)NA * DK + a0 + tid] = 1.0f;
}

// ---------------------------------------------------------------------------
// Launch: inputs (metadata order): a_z, bv_z, mask(bool->int32), weight, Wq, Wk, Wv, h
// ---------------------------------------------------------------------------
extern "C" void kernel_launch(void* const* d_in, const int* in_sizes, int n_in,
                              void* d_out, int out_size) {
    const float* a_z  = (const float*)d_in[0];
    const float* bv_z = (const float*)d_in[1];
    const int*   mask = (const int*)d_in[2];
    const float* weight = (const float*)d_in[3];
    const float* Wq = (const float*)d_in[4];
    const float* Wk = (const float*)d_in[5];
    const float* Wv = (const float*)d_in[6];
    float* out = (float*)d_out;

    dim3 pg(NA / 64, DD / 64, 3);
    proj_kernel<<<pg, 128>>>(a_z, bv_z, Wq, Wk, Wv);
    attn_kernel<<<NA / 32, 128>>>(mask, weight, out);
}

// round 5
// speedup vs baseline: 3.6680x; 3.6680x over previous
#include <cuda_runtime.h>
#include <cuda_fp16.h>
#include <cstdint>

// Problem constants
#define NA 4096
#define NB 4096
#define DD 256
#define HH 4
#define DK 64

// Scratch: projected Q/K/V in fp16 — __device__ globals (no allocs allowed)
__device__ __half g_Q[NA * DD];
__device__ __half g_K[NB * DD];
__device__ __half g_V[NB * DD];

__device__ __forceinline__ void mma16816(float c[4], const uint32_t a[4],
                                         uint32_t b0, uint32_t b1) {
    asm volatile(
        "mma.sync.aligned.m16n8k16.row.col.f32.f16.f16.f32 "
        "{%0,%1,%2,%3}, {%4,%5,%6,%7}, {%8,%9}, {%0,%1,%2,%3};\n"
        : "+f"(c[0]), "+f"(c[1]), "+f"(c[2]), "+f"(c[3])
        : "r"(a[0]), "r"(a[1]), "r"(a[2]), "r"(a[3]), "r"(b0), "r"(b1));
}

__device__ __forceinline__ uint32_t packh2(float x, float y) {
    __half2 t = __floats2half2_rn(x, y);
    return *reinterpret_cast<uint32_t*>(&t);
}

__device__ __forceinline__ void ldsm4(uint32_t r[4], const __half* p) {
    uint32_t a = (uint32_t)__cvta_generic_to_shared(p);
    asm volatile("ldmatrix.sync.aligned.m8n8.x4.shared.b16 {%0,%1,%2,%3}, [%4];\n"
                 : "=r"(r[0]), "=r"(r[1]), "=r"(r[2]), "=r"(r[3]) : "r"(a));
}

__device__ __forceinline__ void ldsm4t(uint32_t r[4], const __half* p) {
    uint32_t a = (uint32_t)__cvta_generic_to_shared(p);
    asm volatile("ldmatrix.sync.aligned.m8n8.x4.trans.shared.b16 {%0,%1,%2,%3}, [%4];\n"
                 : "=r"(r[0]), "=r"(r[1]), "=r"(r[2]), "=r"(r[3]) : "r"(a));
}

__device__ __forceinline__ void cpasync16(void* s, const void* g) {
    uint32_t sa = (uint32_t)__cvta_generic_to_shared(s);
    asm volatile("cp.async.cg.shared.global [%0], [%1], 16;\n" :: "r"(sa), "l"(g));
}
__device__ __forceinline__ void cp_commit() { asm volatile("cp.async.commit_group;\n"); }
__device__ __forceinline__ void cp_wait0() { asm volatile("cp.async.wait_group 0;\n" ::: "memory"); }

// ---------------------------------------------------------------------------
// Kernel 1: projections  Y = X @ W^T  (fp32 in, fp16 out), 3 GEMMs via grid.z
// ---------------------------------------------------------------------------
__global__ __launch_bounds__(128) void proj_kernel(
    const float* __restrict__ a_z, const float* __restrict__ bv_z,
    const float* __restrict__ Wq, const float* __restrict__ Wk,
    const float* __restrict__ Wv) {
    const float* X;
    const float* W;
    __half* Y;
    int z = blockIdx.z;
    if (z == 0)      { X = a_z;  W = Wq; Y = g_Q; }
    else if (z == 1) { X = bv_z; W = Wk; Y = g_K; }
    else             { X = bv_z; W = Wv; Y = g_V; }

    const int a0 = blockIdx.x * 64;
    const int n0 = blockIdx.y * 64;

    __shared__ __half sA[64][24];
    __shared__ __half sB[64][24];

    const int tid = threadIdx.x;
    const int lane = tid & 31, warp = tid >> 5;
    const int gr = lane >> 2, tig = lane & 3;
    const int wm = warp >> 1, wn = warp & 1;

    float acc[2][4][4] = {};

    for (int kt = 0; kt < DD / 16; kt++) {
        __syncthreads();
#pragma unroll
        for (int i = 0; i < 2; i++) {
            int j = tid + i * 128;
            int row = j >> 2, c4 = (j & 3) * 4;
            float4 xa = *(const float4*)&X[(size_t)(a0 + row) * DD + kt * 16 + c4];
            *(__half2*)&sA[row][c4]     = __floats2half2_rn(xa.x, xa.y);
            *(__half2*)&sA[row][c4 + 2] = __floats2half2_rn(xa.z, xa.w);
            float4 xb = *(const float4*)&W[(size_t)(n0 + row) * DD + kt * 16 + c4];
            *(__half2*)&sB[row][c4]     = __floats2half2_rn(xb.x, xb.y);
            *(__half2*)&sB[row][c4 + 2] = __floats2half2_rn(xb.z, xb.w);
        }
        __syncthreads();

        uint32_t af[2][4];
#pragma unroll
        for (int mt = 0; mt < 2; mt++) {
            const __half* p = &sA[wm * 32 + mt * 16 + gr][tig * 2];
            af[mt][0] = *(const uint32_t*)p;
            af[mt][1] = *(const uint32_t*)(p + 8 * 24);
            af[mt][2] = *(const uint32_t*)(p + 8);
            af[mt][3] = *(const uint32_t*)(p + 8 * 24 + 8);
        }
#pragma unroll
        for (int nt = 0; nt < 4; nt++) {
            const __half* p = &sB[wn * 32 + nt * 8 + gr][tig * 2];
            uint32_t b0 = *(const uint32_t*)p;
            uint32_t b1 = *(const uint32_t*)(p + 8);
            mma16816(acc[0][nt], af[0], b0, b1);
            mma16816(acc[1][nt], af[1], b0, b1);
        }
    }

#pragma unroll
    for (int mt = 0; mt < 2; mt++)
#pragma unroll
        for (int nt = 0; nt < 4; nt++) {
            int row = a0 + wm * 32 + mt * 16 + gr;
            int col = n0 + wn * 32 + nt * 8 + tig * 2;
            *(__half2*)&Y[(size_t)row * DD + col] = __floats2half2_rn(acc[mt][nt][0], acc[mt][nt][1]);
            *(__half2*)&Y[(size_t)(row + 8) * DD + col] = __floats2half2_rn(acc[mt][nt][2], acc[mt][nt][3]);
        }
}

// ---------------------------------------------------------------------------
// Kernel 2: fused attention v2.
// 128 CTAs x 256 threads (8 warps). warp = (head h = w&3, m-half mh = w>>2).
// BM=32 a-rows/CTA, loop 128 b-tiles of BN=32. Double-buffered cp.async staging,
// ldmatrix frag loads (V via .trans — no smem transpose), den via MMA-with-ones.
// ---------------------------------------------------------------------------
#define KSTRIDE 264                      // halves per K/V row (512B data + 16B pad)
#define KBUF_HALVES (32 * KSTRIDE)       // 8448 halves = 16896 B
#define WSTRIDE 36                       // floats per sW row

#define OFF_V (2 * KBUF_HALVES * 2)      // 33792 B
#define OFF_W (OFF_V + 2 * KBUF_HALVES * 2)  // 67584 B
#define SMEM_TOTAL (OFF_W + 2 * 32 * WSTRIDE * 4)  // 67584 + 9216 = 76800 B

#define ONESH2 0x3C003C00u               // half2 {1.0, 1.0}

__global__ __launch_bounds__(256) void attn_kernel(
    const int* __restrict__ mask, const float* __restrict__ weight,
    float* __restrict__ out) {
    extern __shared__ __align__(16) unsigned char smem[];
    __half* sK = reinterpret_cast<__half*>(smem);
    __half* sV = reinterpret_cast<__half*>(smem + OFF_V);
    float*  sW = reinterpret_cast<float*>(smem + OFF_W);

    const int tid = threadIdx.x;
    const int lane = tid & 31;
    const int w = tid >> 5;
    const int h = w & 3;                 // head
    const int mh = w >> 2;               // m-half: rows mh*16 .. mh*16+15
    const int gr = lane >> 2, tig = lane & 3;
    const int a0 = blockIdx.x * 32;

    // Q fragments (1 m-tile of 16 rows, 4 k-steps)
    uint32_t qf[4][4];
#pragma unroll
    for (int ks = 0; ks < 4; ks++) {
        const __half* q = &g_Q[(size_t)(a0 + mh * 16 + gr) * DD + h * DK + ks * 16 + tig * 2];
        qf[ks][0] = *(const uint32_t*)q;
        qf[ks][1] = *(const uint32_t*)(q + 8 * DD);
        qf[ks][2] = *(const uint32_t*)(q + 8);
        qf[ks][3] = *(const uint32_t*)(q + 8 * DD + 8);
    }

    float cacc[8][4] = {};   // context numerator: 8 d-blocks x c-frag
    float denacc[4] = {};    // den via MMA-ones: [0]=row gr, [2]=row gr+8

    // W/mask fold geometry: thread -> one float4 of the 32x32 weight tile
    const int wrow = tid >> 3, wc4 = (tid & 7) * 4;

    // ---- prologue: stage tile 0 ----
    {
        __half* kb = sK;  __half* vb = sV;
#pragma unroll
        for (int i = 0; i < 4; i++) {
            int j = tid + i * 256;
            int row = j >> 5, ch = (j & 31) * 8;
            cpasync16(&kb[row * KSTRIDE + ch], &g_K[(size_t)row * DD + ch]);
            cpasync16(&vb[row * KSTRIDE + ch], &g_V[(size_t)row * DD + ch]);
        }
        cp_commit();
        float4 w4 = *(const float4*)&weight[(size_t)(a0 + wrow) * NB + wc4];
        int4   m4 = *(const int4*)&mask[(size_t)(a0 + wrow) * NB + wc4];
        float4 f;
        f.x = m4.x ? w4.x : -1e30f;
        f.y = m4.y ? w4.y : -1e30f;
        f.z = m4.z ? w4.z : -1e30f;
        f.w = m4.w ? w4.w : -1e30f;
        *(float4*)&sW[wrow * WSTRIDE + wc4] = f;
    }

    for (int t = 0; t < NB / 32; t++) {
        cp_wait0();
        __syncthreads();

        const int buf = t & 1;
        const __half* kb = sK + buf * KBUF_HALVES;
        const __half* vb = sV + buf * KBUF_HALVES;
        const float*  wb = sW + buf * 32 * WSTRIDE;

        // ---- prefetch tile t+1 (cp.async) + W regs ----
        float4 wreg; int4 mreg;
        const bool pre = (t + 1) < NB / 32;
        if (pre) {
            const int b1 = (t + 1) * 32;
            __half* kn = sK + ((t + 1) & 1) * KBUF_HALVES;
            __half* vn = sV + ((t + 1) & 1) * KBUF_HALVES;
#pragma unroll
            for (int i = 0; i < 4; i++) {
                int j = tid + i * 256;
                int row = j >> 5, ch = (j & 31) * 8;
                cpasync16(&kn[row * KSTRIDE + ch], &g_K[(size_t)(b1 + row) * DD + ch]);
                cpasync16(&vn[row * KSTRIDE + ch], &g_V[(size_t)(b1 + row) * DD + ch]);
            }
            cp_commit();
            wreg = *(const float4*)&weight[(size_t)(a0 + wrow) * NB + b1 + wc4];
            mreg = *(const int4*)&mask[(size_t)(a0 + wrow) * NB + b1 + wc4];
        }

        // ---- S = Q K^T (16 x 32 per warp) ----
        float sacc[4][4] = {};
#pragma unroll
        for (int nt = 0; nt < 4; nt++) {
            uint32_t kf[8];
            const __half* p1 = &kb[(nt * 8 + (lane & 7)) * KSTRIDE + h * DK + (lane >> 3) * 8];
            ldsm4(kf, p1);
            ldsm4(kf + 4, p1 + 32);
            mma16816(sacc[nt], qf[0], kf[0], kf[1]);
            mma16816(sacc[nt], qf[1], kf[2], kf[3]);
            mma16816(sacc[nt], qf[2], kf[4], kf[5]);
            mma16816(sacc[nt], qf[3], kf[6], kf[7]);
        }

        // ---- epilogue: t = clip(s/8 + w', -10, 10); p = exp(t); pack as A-frag ----
        uint32_t pa[2][4];
#pragma unroll
        for (int nt = 0; nt < 4; nt++) {
            const float* wp0 = &wb[(mh * 16 + gr) * WSTRIDE + nt * 8 + tig * 2];
            float2 w0 = *(const float2*)wp0;
            float2 w1 = *(const float2*)(wp0 + 8 * WSTRIDE);
            float p0 = __expf(fmaxf(fminf(sacc[nt][0] * 0.125f + w0.x, 10.f), -10.f));
            float p1 = __expf(fmaxf(fminf(sacc[nt][1] * 0.125f + w0.y, 10.f), -10.f));
            float p2 = __expf(fmaxf(fminf(sacc[nt][2] * 0.125f + w1.x, 10.f), -10.f));
            float p3 = __expf(fmaxf(fminf(sacc[nt][3] * 0.125f + w1.y, 10.f), -10.f));
            int kk = nt >> 1, hf = nt & 1;
            pa[kk][hf * 2 + 0] = packh2(p0, p1);
            pa[kk][hf * 2 + 1] = packh2(p2, p3);
        }

        // ---- den += P @ ones (same fp16 P as numerator -> errors cancel in ratio) ----
        mma16816(denacc, pa[0], ONESH2, ONESH2);
        mma16816(denacc, pa[1], ONESH2, ONESH2);

        // ---- context += P @ V (V B-frags via ldmatrix.trans on row-major sV) ----
#pragma unroll
        for (int nt2 = 0; nt2 < 8; nt2++) {
            uint32_t vf[4];
            ldsm4t(vf, &vb[lane * KSTRIDE + h * DK + nt2 * 8]);
            mma16816(cacc[nt2], pa[0], vf[0], vf[1]);
            mma16816(cacc[nt2], pa[1], vf[2], vf[3]);
        }

        // ---- store folded W for tile t+1 (visible after next sync) ----
        if (pre) {
            float4 f;
            f.x = mreg.x ? wreg.x : -1e30f;
            f.y = mreg.y ? wreg.y : -1e30f;
            f.z = mreg.z ? wreg.z : -1e30f;
            f.w = mreg.w ? wreg.w : -1e30f;
            *(float4*)&sW[((t + 1) & 1) * 32 * WSTRIDE + wrow * WSTRIDE + wc4] = f;
        }
    }

    const float inv0 = 1.0f / denacc[0];
    const float inv1 = 1.0f / denacc[2];

    __syncthreads();  // all warps done with staging smem before ctx reuse
    float* ctx = reinterpret_cast<float*>(smem);  // [4 heads][32 rows][68]
#pragma unroll
    for (int nt2 = 0; nt2 < 8; nt2++) {
        int r0 = h * 32 + mh * 16 + gr;
        int dc = nt2 * 8 + tig * 2;
        ctx[(size_t)r0 * 68 + dc]           = cacc[nt2][0] * inv0;
        ctx[(size_t)r0 * 68 + dc + 1]       = cacc[nt2][1] * inv0;
        ctx[(size_t)(r0 + 8) * 68 + dc]     = cacc[nt2][2] * inv1;
        ctx[(size_t)(r0 + 8) * 68 + dc + 1] = cacc[nt2][3] * inv1;
    }
    __syncthreads();

#pragma unroll
    for (int i = 0; i < 8; i++) {
        int e = tid + i * 256;
        int a = e >> 6, dc = e & 63;
        out[(size_t)(a0 + a) * DK + dc] =
            0.25f * (ctx[(size_t)a * 68 + dc] + ctx[(size_t)(32 + a) * 68 + dc] +
                     ctx[(size_t)(64 + a) * 68 + dc] + ctx[(size_t)(96 + a) * 68 + dc]);
    }
    if (tid < 32) out[(size_t)NA * DK + a0 + tid] = 1.0f;
}

// ---------------------------------------------------------------------------
// Launch: inputs (metadata order): a_z, bv_z, mask(bool->int32), weight, Wq, Wk, Wv, h
// ---------------------------------------------------------------------------
extern "C" void kernel_launch(void* const* d_in, const int* in_sizes, int n_in,
                              void* d_out, int out_size) {
    const float* a_z  = (const float*)d_in[0];
    const float* bv_z = (const float*)d_in[1];
    const int*   mask = (const int*)d_in[2];
    const float* weight = (const float*)d_in[3];
    const float* Wq = (const float*)d_in[4];
    const float* Wk = (const float*)d_in[5];
    const float* Wv = (const float*)d_in[6];
    float* out = (float*)d_out;

    cudaFuncSetAttribute(attn_kernel, cudaFuncAttributeMaxDynamicSharedMemorySize, SMEM_TOTAL);

    dim3 pg(NA / 64, DD / 64, 3);
    proj_kernel<<<pg, 128>>>(a_z, bv_z, Wq, Wk, Wv);
    attn_kernel<<<NA / 32, 256, SMEM_TOTAL>>>(mask, weight, out);
}